// round 10
// baseline (speedup 1.0000x reference)
#include <cuda_runtime.h>
#include <math.h>

#define NN  32768
#define EE  524288
#define BB  32
#define K1c 512
#define K2c 256
#define BK1 16384   // BB*K1
#define BK2 8192    // BB*K2
#define FH  128

// ---------------- scratch ----------------
__device__ float g_t[NN*FH];
__device__ float g_h1[NN*FH];
__device__ float g_a[NN*FH];
__device__ float g_bf[NN*FH];
__device__ float g_xout[NN*FH];
__device__ float g_xoutF[NN*FH];
__device__ float g_mA[NN*FH];
__device__ float g_mB[NN*64];
__device__ float g_xp1[BK1*FH];
__device__ float g_t2[BK1*FH];
__device__ float g_h2[BK1*FH];
__device__ float g_xo2[BK1*FH];
__device__ float g_xp2[BK2*FH];
__device__ float g_lin[NN];
__device__ float g_sc1[NN];
__device__ float g_sc2[BK1];
__device__ float g_deggt[NN];
__device__ float g_xdeg[NN];
__device__ float g_dinv1[NN], g_invd1[NN];
__device__ float g_dinv2[BK1], g_invd2[BK1];
__device__ int   g_cntD[NN], g_cntS[NN], g_cur1[NN];
__device__ int   g_row1[NN+1];
__device__ int   g_csr1[EE];      // edge ids, then mapped to src
__device__ int   g_cnt2[BK1], g_cur2[BK1];
__device__ int   g_row2[BK1+1];
__device__ int   g_csr2[EE];      // edge ids, then mapped to ns
__device__ int   g_perm1[BK1], g_pos1[NN];
__device__ int   g_perm2[BK2], g_pos2[BK1];
__device__ float g_g1[BB*256], g_g2[BB*256];

// ---------------- XLA:CPU f32 tanh (Eigen generic_fast_tanh_float + XLA tiny-x case) ----------------
__device__ __forceinline__ float xla_tanhf(float x) {
    const float kMax = 7.90531110763549805f;
    float xc = fminf(fmaxf(x, -kMax), kMax);
    float x2 = __fmul_rn(xc, xc);
    float p = fmaf(x2, -2.76076847742355e-16f, 2.00018790482477e-13f);
    p = fmaf(x2, p, -8.60467152213735e-11f);
    p = fmaf(x2, p, 5.12229709037114e-08f);
    p = fmaf(x2, p, 1.48572235717979e-05f);
    p = fmaf(x2, p, 6.37261928875436e-04f);
    p = fmaf(x2, p, 4.89352455891786e-03f);
    p = __fmul_rn(p, xc);
    float q = fmaf(x2, 1.19825839466702e-06f, 1.18534705686654e-04f);
    q = fmaf(x2, q, 2.26843463243900e-03f);
    q = fmaf(x2, q, 4.89352518554385e-03f);
    float r = __fdiv_rn(p, q);
    if (fabsf(x) < 0.0004f) r = x;
    return r;
}

// ---------------- graph prep ----------------

__global__ void zero_counts_kernel() {
    int i = blockIdx.x * blockDim.x + threadIdx.x;
    if (i < NN) { g_cntD[i] = 0; g_cntS[i] = 0; g_cur1[i] = 0; }
    if (i < BK1) { g_cnt2[i] = 0; g_cur2[i] = 0; }
}

__global__ void count_kernel(const int* __restrict__ src, const int* __restrict__ dst) {
    int e = blockIdx.x * blockDim.x + threadIdx.x;
    if (e >= EE) return;
    atomicAdd(&g_cntD[dst[e]], 1);
    atomicAdd(&g_cntS[src[e]], 1);
}

__global__ void degprep1_kernel() {
    int v = blockIdx.x * blockDim.x + threadIdx.x;
    if (v >= NN) return;
    float d = __fadd_rn(1.0f, (float)g_cntD[v]);
    g_dinv1[v] = __fdiv_rn(1.0f, __fsqrt_rn(d));
    g_invd1[v] = __fdiv_rn(1.0f, d);
    g_deggt[v] = (float)g_cntS[v];
}

__global__ void scan_kernel(const int* __restrict__ cnt, int* __restrict__ row, int n) {
    __shared__ int sh[1024];
    int tid = threadIdx.x;
    int chunk = n >> 10;
    int base = tid * chunk;
    int s = 0;
    for (int i = 0; i < chunk; i++) s += cnt[base + i];
    sh[tid] = s;
    __syncthreads();
    for (int off = 1; off < 1024; off <<= 1) {
        int v = (tid >= off) ? sh[tid - off] : 0;
        __syncthreads();
        sh[tid] += v;
        __syncthreads();
    }
    int run = (tid == 0) ? 0 : sh[tid - 1];
    for (int i = 0; i < chunk; i++) { row[base + i] = run; run += cnt[base + i]; }
    if (tid == 1023) row[n] = run;
}

// store EDGE IDs into CSR slots (order arbitrary; canonicalized by sort below)
__global__ void fill1_kernel(const int* __restrict__ src, const int* __restrict__ dst) {
    int e = blockIdx.x * blockDim.x + threadIdx.x;
    if (e >= EE) return;
    int d = dst[e];
    int slot = g_row1[d] + atomicAdd(&g_cur1[d], 1);
    g_csr1[slot] = e;
}

// per-row insertion sort ascending (edge ids) -> deterministic edge order
__global__ void sortrows_kernel(const int* __restrict__ row, int* __restrict__ csr, int n) {
    int v = blockIdx.x * blockDim.x + threadIdx.x;
    if (v >= n) return;
    int beg = row[v], end = row[v + 1];
    for (int i = beg + 1; i < end; i++) {
        int key = csr[i];
        int j = i - 1;
        while (j >= beg && csr[j] > key) { csr[j + 1] = csr[j]; j--; }
        csr[j + 1] = key;
    }
}

// map edge id -> src (level 1)
__global__ void map1_kernel(const int* __restrict__ src) {
    int i = blockIdx.x * blockDim.x + threadIdx.x;
    if (i >= EE) return;
    g_csr1[i] = src[g_csr1[i]];
}

__global__ void count2_kernel(const int* __restrict__ src, const int* __restrict__ dst) {
    int e = blockIdx.x * blockDim.x + threadIdx.x;
    if (e >= EE) return;
    int ns = g_pos1[src[e]];
    int nd = g_pos1[dst[e]];
    if (ns >= 0 && nd >= 0) atomicAdd(&g_cnt2[nd], 1);
}

__global__ void degprep2_kernel() {
    int u = blockIdx.x * blockDim.x + threadIdx.x;
    if (u >= BK1) return;
    float d = __fadd_rn(1.0f, (float)g_cnt2[u]);
    g_dinv2[u] = __fdiv_rn(1.0f, __fsqrt_rn(d));
    g_invd2[u] = __fdiv_rn(1.0f, d);
}

__global__ void fill2_kernel(const int* __restrict__ src, const int* __restrict__ dst) {
    int e = blockIdx.x * blockDim.x + threadIdx.x;
    if (e >= EE) return;
    int ns = g_pos1[src[e]];
    int nd = g_pos1[dst[e]];
    if (ns >= 0 && nd >= 0) {
        int slot = g_row2[nd] + atomicAdd(&g_cur2[nd], 1);
        g_csr2[slot] = e;
    }
}

// map edge id -> ns (level 2); bounded by row2[BK1]
__global__ void map2_kernel(const int* __restrict__ src) {
    int i = blockIdx.x * blockDim.x + threadIdx.x;
    if (i >= g_row2[BK1]) return;
    g_csr2[i] = g_pos1[src[g_csr2[i]]];
}

// ---------------- dense matmul ----------------
// C[M,FOUT] = A[M,128] @ W[128,FOUT] (+bias)(+act).
template<int FOUT>
__global__ void mm_kernel(const float* __restrict__ A, const float* __restrict__ W,
                          const float* __restrict__ bias, float* __restrict__ C, int act) {
    constexpr int CP = FOUT / 32;
    __shared__ float As[64][32];
    __shared__ float Ws[32][FOUT];
    const int tid = threadIdx.x;
    const int rg = tid >> 5;
    const int lane = tid & 31;
    const int m0 = blockIdx.x * 64;

    float accA[8][CP], accB[8][CP];
#pragma unroll
    for (int r = 0; r < 8; r++)
#pragma unroll
        for (int c = 0; c < CP; c++) { accA[r][c] = 0.0f; accB[r][c] = 0.0f; }

    for (int kc = 0; kc < 128; kc += 32) {
        for (int i = tid; i < 512; i += 256) {
            int r = i >> 3, q = i & 7;
            ((float4*)(&As[r][0]))[q] = ((const float4*)(A + (size_t)(m0 + r) * 128 + kc))[q];
        }
        for (int i = tid; i < 32 * FOUT / 4; i += 256) {
            int r = i / (FOUT / 4), q = i % (FOUT / 4);
            ((float4*)(&Ws[r][0]))[q] = ((const float4*)(W + (size_t)(kc + r) * FOUT))[q];
        }
        __syncthreads();
#pragma unroll
        for (int k = 0; k < 32; k += 4) {
            float4 a4[8];
#pragma unroll
            for (int r = 0; r < 8; r++) a4[r] = *(const float4*)&As[rg * 8 + r][k];
#pragma unroll
            for (int kk = 0; kk < 4; kk++) {
                float wv[CP];
                if constexpr (CP == 4) {
                    float4 w4 = *(const float4*)&Ws[k + kk][lane * 4];
                    wv[0] = w4.x; wv[1] = w4.y; wv[2] = w4.z; wv[3] = w4.w;
                } else {
                    float2 w2 = *(const float2*)&Ws[k + kk][lane * 2];
                    wv[0] = w2.x; wv[1] = w2.y;
                }
#pragma unroll
                for (int r = 0; r < 8; r++) {
                    float av = (&a4[r].x)[kk];
                    if ((kk & 1) == 0) {
#pragma unroll
                        for (int c = 0; c < CP; c++) accA[r][c] = fmaf(av, wv[c], accA[r][c]);
                    } else {
#pragma unroll
                        for (int c = 0; c < CP; c++) accB[r][c] = fmaf(av, wv[c], accB[r][c]);
                    }
                }
            }
        }
        __syncthreads();
    }

#pragma unroll
    for (int r = 0; r < 8; r++) {
        int row = m0 + rg * 8 + r;
#pragma unroll
        for (int c = 0; c < CP; c++) {
            float v = __fadd_rn(accA[r][c], accB[r][c]);
            if (bias != nullptr) v = __fadd_rn(v, bias[lane * CP + c]);
            if (act == 1) v = fmaxf(v, 0.0f);
            else if (act == 2) v = xla_tanhf(v);
            C[(size_t)row * FOUT + lane * CP + c] = v;
        }
    }
}

// ---------------- GCN aggregation (sequential edge order, mul then add, no FMA) ----------------
__global__ void agg_kernel(const float* __restrict__ t, const int* __restrict__ row,
                           const int* __restrict__ csr, const float* __restrict__ dinv,
                           const float* __restrict__ invd, const float* __restrict__ bias,
                           float* __restrict__ out, int n, int act) {
    int v = (blockIdx.x * blockDim.x + threadIdx.x) >> 5;
    int lane = threadIdx.x & 31;
    if (v >= n) return;
    int beg = row[v], end = row[v + 1];
    float dv = dinv[v], iv = invd[v];
    float ax = 0.f, ay = 0.f, az = 0.f, aw = 0.f;
    for (int jb = beg; jb < end; jb += 32) {
        int myj = jb + lane;
        int s_l = (myj < end) ? csr[myj] : 0;
        float w_l = (myj < end) ? dinv[s_l] : 0.f;
        int cnt = min(32, end - jb);
        for (int i = 0; i < cnt; i++) {
            int s = __shfl_sync(0xffffffffu, s_l, i);
            float ds = __shfl_sync(0xffffffffu, w_l, i);
            float w = __fmul_rn(ds, dv);                 // norm = dinv[src]*dinv[dst]
            float4 h = *(const float4*)&t[(size_t)s * 128 + lane * 4];
            ax = __fadd_rn(ax, __fmul_rn(h.x, w));
            ay = __fadd_rn(ay, __fmul_rn(h.y, w));
            az = __fadd_rn(az, __fmul_rn(h.z, w));
            aw = __fadd_rn(aw, __fmul_rn(h.w, w));
        }
    }
    float4 tv = *(const float4*)&t[(size_t)v * 128 + lane * 4];
    float4 b4 = *(const float4*)&bias[lane * 4];
    float o0 = __fadd_rn(__fadd_rn(ax, __fmul_rn(tv.x, iv)), b4.x);
    float o1 = __fadd_rn(__fadd_rn(ay, __fmul_rn(tv.y, iv)), b4.y);
    float o2 = __fadd_rn(__fadd_rn(az, __fmul_rn(tv.z, iv)), b4.z);
    float o3 = __fadd_rn(__fadd_rn(aw, __fmul_rn(tv.w, iv)), b4.w);
    if (act == 1) { o0 = fmaxf(o0, 0.f); o1 = fmaxf(o1, 0.f); o2 = fmaxf(o2, 0.f); o3 = fmaxf(o3, 0.f); }
    else if (act == 2) { o0 = xla_tanhf(o0); o1 = xla_tanhf(o1); o2 = xla_tanhf(o2); o3 = xla_tanhf(o3); }
    *(float4*)&out[(size_t)v * 128 + lane * 4] = make_float4(o0, o1, o2, o3);
}

// lin[v] = A[v,:128]·w — 4 strided lanes + Eigen-predux reduce (l0+l2)+(l1+l3)
__global__ void dot128_kernel(const float* __restrict__ A, const float* __restrict__ w,
                              float* __restrict__ out, int M) {
    int v = blockIdx.x * blockDim.x + threadIdx.x;
    if (v >= M) return;
    const float* a = A + (size_t)v * 128;
    float l0 = 0.f, l1 = 0.f, l2 = 0.f, l3 = 0.f;
#pragma unroll 8
    for (int k = 0; k < 128; k += 4) {
        l0 = fmaf(a[k],     __ldg(&w[k]),     l0);
        l1 = fmaf(a[k + 1], __ldg(&w[k + 1]), l1);
        l2 = fmaf(a[k + 2], __ldg(&w[k + 2]), l2);
        l3 = fmaf(a[k + 3], __ldg(&w[k + 3]), l3);
    }
    out[v] = __fadd_rn(__fadd_rn(l0, l2), __fadd_rn(l1, l3));
}

// score[v], fp32, sequential edge order, mul/add separate
__global__ void scoreagg_kernel(const float* __restrict__ lin, const int* __restrict__ row,
                                const int* __restrict__ csr, const float* __restrict__ dinv,
                                const float* __restrict__ invd, const float* __restrict__ bias,
                                float* __restrict__ score, int n) {
    int v = blockIdx.x * blockDim.x + threadIdx.x;
    if (v >= n) return;
    int beg = row[v], end = row[v + 1];
    float dv = dinv[v];
    float acc = 0.0f;
    for (int j = beg; j < end; j++) {
        int s = csr[j];
        float w = __fmul_rn(dinv[s], dv);
        acc = __fadd_rn(acc, __fmul_rn(lin[s], w));
    }
    score[v] = __fadd_rn(__fadd_rn(acc, __fmul_rn(lin[v], invd[v])), bias[0]);
}

// per-graph bitonic sort: fp32 score desc; exact ties -> lower index first.
// Optional near-tie canonicalization with relative threshold thr_rel
// (thr_rel = 0 disables it).
template<int NP>
__global__ void topk_kernel(const float* __restrict__ score, int* __restrict__ perm,
                            int* __restrict__ pos, int kkeep, float thr_rel) {
    __shared__ float ss[NP];
    __shared__ int   si[NP];
    int b = blockIdx.x, tid = threadIdx.x;
    for (int i = tid; i < NP; i += blockDim.x) {
        ss[i] = score[b * NP + i];
        si[i] = i;
        pos[b * NP + i] = -1;
    }
    __syncthreads();
    for (int k = 2; k <= NP; k <<= 1) {
        for (int j = k >> 1; j > 0; j >>= 1) {
            for (int i = tid; i < NP; i += blockDim.x) {
                int ixj = i ^ j;
                if (ixj > i) {
                    float sa = ss[i], sb = ss[ixj];
                    int ia = si[i], ib = si[ixj];
                    bool b_first = (sb > sa) || (sb == sa && ib < ia);
                    bool a_first = (sa > sb) || (sa == sb && ia < ib);
                    bool sw = ((i & k) == 0) ? b_first : a_first;
                    if (sw) { ss[i] = sb; ss[ixj] = sa; si[i] = ib; si[ixj] = ia; }
                }
            }
            __syncthreads();
        }
    }
    // near-tie canonicalization (deterministic serial bubble passes); no-op if thr_rel == 0
    if (tid == 0 && thr_rel > 0.0f) {
        for (int pass = 0; pass < 6; pass++) {
            bool any = false;
            for (int p = 0; p < NP - 1; p++) {
                float a = ss[p], c = ss[p + 1];
                if (a > c) {
                    float gap = __fadd_rn(a, -c);
                    float thr = thr_rel * fmaxf(fabsf(a), fabsf(c));
                    if (gap <= thr && si[p] > si[p + 1]) {
                        ss[p] = c; ss[p + 1] = a;
                        int t2 = si[p]; si[p] = si[p + 1]; si[p + 1] = t2;
                        any = true;
                    }
                }
            }
            if (!any) break;
        }
    }
    __syncthreads();
    for (int i = tid; i < kkeep; i += blockDim.x) {
        int g = b * NP + si[i];
        perm[b * kkeep + i] = g;
        pos[g] = b * kkeep + i;
    }
}

__global__ void gate_kernel(const float* __restrict__ h, const float* __restrict__ score,
                            const int* __restrict__ perm, float* __restrict__ xp, int rows) {
    int gid = blockIdx.x * blockDim.x + threadIdx.x;
    if (gid >= rows * 128) return;
    int j = gid >> 7, c = gid & 127;
    int v = perm[j];
    float tg = xla_tanhf(score[v]);
    xp[gid] = __fmul_rn(h[(size_t)v * 128 + c], tg);
}

__global__ void unpool_kernel(const float* __restrict__ xp, const int* __restrict__ pos,
                              float* __restrict__ out, int rows) {
    int gid = blockIdx.x * blockDim.x + threadIdx.x;
    if (gid >= rows * 128) return;
    int v = gid >> 7, c = gid & 127;
    int p = pos[v];
    out[gid] = (p >= 0) ? xp[(size_t)p * 128 + c] : 0.0f;
}

__global__ void pool_stats_kernel(const float* __restrict__ xp, float* __restrict__ g, int kk) {
    int b = blockIdx.x, c = threadIdx.x;
    float mx = -3.402823466e38f, sm = 0.f;
    const float* base = xp + (size_t)b * kk * 128;
    for (int r = 0; r < kk; r++) {
        float v = base[(size_t)r * 128 + c];
        mx = fmaxf(mx, v);
        sm = __fadd_rn(sm, v);
    }
    g[b * 256 + c] = mx;
    g[b * 256 + 128 + c] = __fdiv_rn(sm, (float)kk);
}

__global__ void gather_kernel(const int* __restrict__ perm, float* __restrict__ og,
                              float* __restrict__ op, int cnt) {
    int j = blockIdx.x * blockDim.x + threadIdx.x;
    if (j >= cnt) return;
    int v = perm[j];
    og[j] = g_deggt[v];
    op[j] = g_xdeg[v];
}

__global__ void mlp641_kernel(const float* __restrict__ in, const float* __restrict__ w,
                              const float* __restrict__ bptr, float* __restrict__ out, int M) {
    int v = blockIdx.x * blockDim.x + threadIdx.x;
    if (v >= M) return;
    const float* a = in + (size_t)v * 64;
    float l0 = 0.f, l1 = 0.f, l2 = 0.f, l3 = 0.f;
#pragma unroll
    for (int k = 0; k < 64; k += 4) {
        l0 = fmaf(a[k],     __ldg(&w[k]),     l0);
        l1 = fmaf(a[k + 1], __ldg(&w[k + 1]), l1);
        l2 = fmaf(a[k + 2], __ldg(&w[k + 2]), l2);
        l3 = fmaf(a[k + 3], __ldg(&w[k + 3]), l3);
    }
    float acc = __fadd_rn(__fadd_rn(l0, l2), __fadd_rn(l1, l3));
    acc = __fadd_rn(acc, bptr[0]);
    out[v] = fmaxf(acc, 0.f);
}

__global__ void head_kernel(const float* __restrict__ wl1, const float* __restrict__ bl1,
                            const float* __restrict__ wl2, const float* __restrict__ bl2,
                            const float* __restrict__ wl3, const float* __restrict__ bl3,
                            float* __restrict__ ocls) {
    __shared__ float gg[256];
    __shared__ float ga[128];
    __shared__ float gb[64];
    int b = blockIdx.x, t = threadIdx.x;
    gg[t]       = g_g1[b * 256 + t]       + g_g2[b * 256 + t];
    gg[t + 128] = g_g1[b * 256 + 128 + t] + g_g2[b * 256 + 128 + t];
    __syncthreads();
    float acc = 0.0f;
    for (int k = 0; k < 256; k++) acc = fmaf(gg[k], wl1[k * 128 + t], acc);
    ga[t] = fmaxf(acc + bl1[t], 0.f);
    __syncthreads();
    if (t < 64) {
        float a2 = 0.0f;
        for (int k = 0; k < 128; k++) a2 = fmaf(ga[k], wl2[k * 64 + t], a2);
        gb[t] = fmaxf(a2 + bl2[t], 0.f);
    }
    __syncthreads();
    if (t < 10) {
        float a3 = 0.0f;
        for (int k = 0; k < 64; k++) a3 = fmaf(gb[k], wl3[k * 10 + t], a3);
        ocls[b * 10 + t] = a3 + bl3[t];
    }
}

// ---------------- host ----------------
static void* devp(const void* sym) {
    void* p = nullptr;
    cudaGetSymbolAddress(&p, sym);
    return p;
}

extern "C" void kernel_launch(void* const* d_in, const int* in_sizes, int n_in,
                              void* d_out, int out_size) {
    const float* x     = (const float*)d_in[0];
    const int*   esrc  = (const int*)d_in[1];
    const int*   edst  = (const int*)d_in[2];
    const float* w_c1 = (const float*)d_in[3];  const float* b_c1 = (const float*)d_in[4];
    const float* w_c2 = (const float*)d_in[5];  const float* b_c2 = (const float*)d_in[6];
    const float* w_c3 = (const float*)d_in[7];  const float* b_c3 = (const float*)d_in[8];
    const float* w_c4 = (const float*)d_in[9];  const float* b_c4 = (const float*)d_in[10];
    const float* w_c5 = (const float*)d_in[11]; const float* b_c5 = (const float*)d_in[12];
    const float* w_p1 = (const float*)d_in[13]; const float* b_p1 = (const float*)d_in[14];
    const float* w_p2 = (const float*)d_in[15]; const float* b_p2 = (const float*)d_in[16];
    const float* w_l1 = (const float*)d_in[17]; const float* b_l1 = (const float*)d_in[18];
    const float* w_l2 = (const float*)d_in[19]; const float* b_l2 = (const float*)d_in[20];
    const float* w_l3 = (const float*)d_in[21]; const float* b_l3 = (const float*)d_in[22];
    const float* w_l4 = (const float*)d_in[23]; const float* b_l4 = (const float*)d_in[24];
    const float* w_l5 = (const float*)d_in[25]; const float* b_l5 = (const float*)d_in[26];
    const float* w_l6 = (const float*)d_in[27]; const float* b_l6 = (const float*)d_in[28];

    float* out = (float*)d_out;
    float* o_cls  = out;
    float* o_dec1 = out + 320;
    float* o_dec2 = o_dec1 + (size_t)NN * FH;
    float* o_dgt1 = o_dec2 + (size_t)NN * FH;
    float* o_dpr1 = o_dgt1 + BK1;
    float* o_dgt2 = o_dpr1 + BK1;
    float* o_dpr2 = o_dgt2 + BK2;

    float* p_t     = (float*)devp(g_t);
    float* p_h1    = (float*)devp(g_h1);
    float* p_a     = (float*)devp(g_a);
    float* p_bf    = (float*)devp(g_bf);
    float* p_xout  = (float*)devp(g_xout);
    float* p_xoutF = (float*)devp(g_xoutF);
    float* p_mA    = (float*)devp(g_mA);
    float* p_mB    = (float*)devp(g_mB);
    float* p_xp1   = (float*)devp(g_xp1);
    float* p_t2    = (float*)devp(g_t2);
    float* p_h2    = (float*)devp(g_h2);
    float* p_xo2   = (float*)devp(g_xo2);
    float* p_xp2   = (float*)devp(g_xp2);
    float* p_lin   = (float*)devp(g_lin);
    float* p_sc1   = (float*)devp(g_sc1);
    float* p_sc2   = (float*)devp(g_sc2);
    float* p_xdeg  = (float*)devp(g_xdeg);
    float* p_dinv1 = (float*)devp(g_dinv1);
    float* p_invd1 = (float*)devp(g_invd1);
    float* p_dinv2 = (float*)devp(g_dinv2);
    float* p_invd2 = (float*)devp(g_invd2);
    int*   p_cntD  = (int*)devp(g_cntD);
    int*   p_row1  = (int*)devp(g_row1);
    int*   p_csr1  = (int*)devp(g_csr1);
    int*   p_cnt2  = (int*)devp(g_cnt2);
    int*   p_row2  = (int*)devp(g_row2);
    int*   p_csr2  = (int*)devp(g_csr2);
    int*   p_perm1 = (int*)devp(g_perm1);
    int*   p_pos1  = (int*)devp(g_pos1);
    int*   p_perm2 = (int*)devp(g_perm2);
    int*   p_pos2  = (int*)devp(g_pos2);
    float* p_g1    = (float*)devp(g_g1);
    float* p_g2    = (float*)devp(g_g2);

    // ---- graph preprocessing (level 1) ----
    zero_counts_kernel<<<NN / 256, 256>>>();
    count_kernel<<<EE / 256, 256>>>(esrc, edst);
    degprep1_kernel<<<NN / 256, 256>>>();
    scan_kernel<<<1, 1024>>>(p_cntD, p_row1, NN);
    fill1_kernel<<<EE / 256, 256>>>(esrc, edst);
    sortrows_kernel<<<NN / 256, 256>>>(p_row1, p_csr1, NN);
    map1_kernel<<<EE / 256, 256>>>(esrc);

    // ---- h1 = relu(gcn(x, w_c1)) ----
    mm_kernel<128><<<NN / 64, 256>>>(x, w_c1, nullptr, p_t, 0);
    agg_kernel<<<NN / 8, 256>>>(p_t, p_row1, p_csr1, p_dinv1, p_invd1, b_c1, p_h1, NN, 1);

    // ---- SAGPool level 1 ----
    dot128_kernel<<<NN / 256, 256>>>(p_h1, w_p1, p_lin, NN);
    scoreagg_kernel<<<NN / 256, 256>>>(p_lin, p_row1, p_csr1, p_dinv1, p_invd1, b_p1, p_sc1, NN);
    topk_kernel<1024><<<BB, 512>>>(p_sc1, p_perm1, p_pos1, K1c, 6e-7f);
    gate_kernel<<<(BK1 * 128) / 256, 256>>>(p_h1, p_sc1, p_perm1, p_xp1, BK1);
    unpool_kernel<<<(NN * 128) / 256, 256>>>(p_xp1, p_pos1, p_xout, NN);

    // ---- decoder 1 -> o_dec1 ----
    mm_kernel<128><<<NN / 64, 256>>>(p_xout, w_c3, nullptr, p_t, 0);
    agg_kernel<<<NN / 8, 256>>>(p_t, p_row1, p_csr1, p_dinv1, p_invd1, b_c3, p_a, NN, 2);
    mm_kernel<128><<<NN / 64, 256>>>(p_a, w_c4, nullptr, p_t, 0);
    agg_kernel<<<NN / 8, 256>>>(p_t, p_row1, p_csr1, p_dinv1, p_invd1, b_c4, p_bf, NN, 2);
    mm_kernel<128><<<NN / 64, 256>>>(p_bf, w_c5, nullptr, p_t, 0);
    agg_kernel<<<NN / 8, 256>>>(p_t, p_row1, p_csr1, p_dinv1, p_invd1, b_c5, o_dec1, NN, 0);

    // ---- degree mlp ----
    mm_kernel<128><<<NN / 64, 256>>>(p_xout, w_l4, b_l4, p_mA, 1);
    mm_kernel<64><<<NN / 64, 256>>>(p_mA, w_l5, b_l5, p_mB, 1);
    mlp641_kernel<<<NN / 256, 256>>>(p_mB, w_l6, b_l6, p_xdeg, NN);
    gather_kernel<<<BK1 / 256, 256>>>(p_perm1, o_dgt1, o_dpr1, BK1);
    pool_stats_kernel<<<BB, 128>>>(p_xp1, p_g1, K1c);

    // ---- level 2 graph ----
    count2_kernel<<<EE / 256, 256>>>(esrc, edst);
    degprep2_kernel<<<BK1 / 256, 256>>>();
    scan_kernel<<<1, 1024>>>(p_cnt2, p_row2, BK1);
    fill2_kernel<<<EE / 256, 256>>>(esrc, edst);
    sortrows_kernel<<<BK1 / 256, 256>>>(p_row2, p_csr2, BK1);
    map2_kernel<<<EE / 256, 256>>>(esrc);

    // h2 = relu(gcn(xp1, w_c2))
    mm_kernel<128><<<BK1 / 64, 256>>>(p_xp1, w_c2, nullptr, p_t2, 0);
    agg_kernel<<<BK1 / 8, 256>>>(p_t2, p_row2, p_csr2, p_dinv2, p_invd2, b_c2, p_h2, BK1, 1);

    // SAGPool level 2 (NO near-tie canonicalization: pure fp32 order + exact-tie lower-index)
    dot128_kernel<<<BK1 / 256, 256>>>(p_h2, w_p2, p_lin, BK1);
    scoreagg_kernel<<<BK1 / 256, 256>>>(p_lin, p_row2, p_csr2, p_dinv2, p_invd2, b_p2, p_sc2, BK1);
    topk_kernel<512><<<BB, 512>>>(p_sc2, p_perm2, p_pos2, K2c, 0.0f);
    gate_kernel<<<(BK2 * 128) / 256, 256>>>(p_h2, p_sc2, p_perm2, p_xp2, BK2);
    unpool_kernel<<<(BK1 * 128) / 256, 256>>>(p_xp2, p_pos2, p_xo2, BK1);
    unpool_kernel<<<(NN * 128) / 256, 256>>>(p_xo2, p_pos1, p_xoutF, NN);
    gather_kernel<<<BK2 / 256, 256>>>(p_perm2, o_dgt2, o_dpr2, BK2);
    pool_stats_kernel<<<BB, 128>>>(p_xp2, p_g2, K2c);

    // ---- decoder 2 -> o_dec2 ----
    mm_kernel<128><<<NN / 64, 256>>>(p_xoutF, w_c3, nullptr, p_t, 0);
    agg_kernel<<<NN / 8, 256>>>(p_t, p_row1, p_csr1, p_dinv1, p_invd1, b_c3, p_a, NN, 2);
    mm_kernel<128><<<NN / 64, 256>>>(p_a, w_c4, nullptr, p_t, 0);
    agg_kernel<<<NN / 8, 256>>>(p_t, p_row1, p_csr1, p_dinv1, p_invd1, b_c4, p_bf, NN, 2);
    mm_kernel<128><<<NN / 64, 256>>>(p_bf, w_c5, nullptr, p_t, 0);
    agg_kernel<<<NN / 8, 256>>>(p_t, p_row1, p_csr1, p_dinv1, p_invd1, b_c5, o_dec2, NN, 0);

    // ---- classification head ----
    head_kernel<<<BB, 128>>>(w_l1, b_l1, w_l2, b_l2, w_l3, b_l3, o_cls);
}

// round 11
// speedup vs baseline: 1.0603x; 1.0603x over previous
#include <cuda_runtime.h>
#include <math.h>

#define NN  32768
#define EE  524288
#define BB  32
#define K1c 512
#define K2c 256
#define BK1 16384   // BB*K1
#define BK2 8192    // BB*K2
#define FH  128

// ---------------- scratch ----------------
__device__ float g_t[NN*FH];
__device__ float g_h1[NN*FH];
__device__ float g_a[NN*FH];
__device__ float g_bf[NN*FH];
__device__ float g_xout[NN*FH];
__device__ float g_xoutF[NN*FH];
__device__ float g_mA[NN*FH];
__device__ float g_mB[NN*64];
__device__ float g_xp1[BK1*FH];
__device__ float g_t2[BK1*FH];
__device__ float g_h2[BK1*FH];
__device__ float g_xp2[BK2*FH];
__device__ float g_lin[NN];
__device__ float g_sc1[NN];
__device__ float g_sc2[BK1];
__device__ float g_deggt[NN];
__device__ float g_xdeg[NN];
__device__ float g_dinv1[NN], g_invd1[NN];
__device__ float g_dinv2[BK1], g_invd2[BK1];
__device__ int   g_cntD[NN], g_cntS[NN], g_cur1[NN];
__device__ int   g_row1[NN+1];
__device__ int   g_csr1[EE];      // edge ids, then mapped to src
__device__ int   g_cnt2[BK1], g_cur2[BK1];
__device__ int   g_row2[BK1+1];
__device__ int   g_csr2[EE];      // edge ids, then mapped to ns
__device__ int   g_perm1[BK1], g_pos1[NN];
__device__ int   g_perm2[BK2], g_pos2[BK1];
__device__ float g_g1[BB*256], g_g2[BB*256];

// ---------------- XLA:CPU f32 tanh ----------------
__device__ __forceinline__ float xla_tanhf(float x) {
    const float kMax = 7.90531110763549805f;
    float xc = fminf(fmaxf(x, -kMax), kMax);
    float x2 = __fmul_rn(xc, xc);
    float p = fmaf(x2, -2.76076847742355e-16f, 2.00018790482477e-13f);
    p = fmaf(x2, p, -8.60467152213735e-11f);
    p = fmaf(x2, p, 5.12229709037114e-08f);
    p = fmaf(x2, p, 1.48572235717979e-05f);
    p = fmaf(x2, p, 6.37261928875436e-04f);
    p = fmaf(x2, p, 4.89352455891786e-03f);
    p = __fmul_rn(p, xc);
    float q = fmaf(x2, 1.19825839466702e-06f, 1.18534705686654e-04f);
    q = fmaf(x2, q, 2.26843463243900e-03f);
    q = fmaf(x2, q, 4.89352518554385e-03f);
    float r = __fdiv_rn(p, q);
    if (fabsf(x) < 0.0004f) r = x;
    return r;
}

// ---------------- graph prep ----------------

__global__ void zero_counts_kernel() {
    int i = blockIdx.x * blockDim.x + threadIdx.x;
    if (i < NN) { g_cntD[i] = 0; g_cntS[i] = 0; g_cur1[i] = 0; }
    if (i < BK1) { g_cnt2[i] = 0; g_cur2[i] = 0; }
}

__global__ void count_kernel(const int* __restrict__ src, const int* __restrict__ dst) {
    int e = blockIdx.x * blockDim.x + threadIdx.x;
    if (e >= EE) return;
    atomicAdd(&g_cntD[dst[e]], 1);
    atomicAdd(&g_cntS[src[e]], 1);
}

__global__ void degprep1_kernel() {
    int v = blockIdx.x * blockDim.x + threadIdx.x;
    if (v >= NN) return;
    float d = __fadd_rn(1.0f, (float)g_cntD[v]);
    g_dinv1[v] = __fdiv_rn(1.0f, __fsqrt_rn(d));
    g_invd1[v] = __fdiv_rn(1.0f, d);
    g_deggt[v] = (float)g_cntS[v];
}

// fast single-block exclusive scan (integer-exact, warp shuffles)
template<int N>
__global__ void scan_kernel(const int* __restrict__ cnt, int* __restrict__ row) {
    constexpr int CH = N / 1024;
    __shared__ int warpsum[32];
    int tid = threadIdx.x;
    int lane = tid & 31, wid = tid >> 5;
    int base = tid * CH;
    int vals[CH];
#pragma unroll
    for (int i = 0; i < CH; i += 4) {
        int4 v4 = *(const int4*)&cnt[base + i];
        vals[i] = v4.x; vals[i+1] = v4.y; vals[i+2] = v4.z; vals[i+3] = v4.w;
    }
    int tot = 0;
#pragma unroll
    for (int i = 0; i < CH; i++) tot += vals[i];
    int sc = tot;
#pragma unroll
    for (int o = 1; o < 32; o <<= 1) {
        int u = __shfl_up_sync(0xffffffffu, sc, o);
        if (lane >= o) sc += u;
    }
    if (lane == 31) warpsum[wid] = sc;
    __syncthreads();
    if (wid == 0) {
        int ws = warpsum[lane];
#pragma unroll
        for (int o = 1; o < 32; o <<= 1) {
            int u = __shfl_up_sync(0xffffffffu, ws, o);
            if (lane >= o) ws += u;
        }
        warpsum[lane] = ws;
    }
    __syncthreads();
    int run = sc - tot + (wid > 0 ? warpsum[wid - 1] : 0);
#pragma unroll
    for (int i = 0; i < CH; i++) { row[base + i] = run; run += vals[i]; }
    if (tid == 1023) row[N] = run;
}

__global__ void fill1_kernel(const int* __restrict__ src, const int* __restrict__ dst) {
    int e = blockIdx.x * blockDim.x + threadIdx.x;
    if (e >= EE) return;
    int d = dst[e];
    int slot = g_row1[d] + atomicAdd(&g_cur1[d], 1);
    g_csr1[slot] = e;
}

// fused: per-row insertion sort of edge ids, then map edge id -> src
__global__ void sortmap1_kernel(const int* __restrict__ row, int* __restrict__ csr,
                                const int* __restrict__ src, int n) {
    int v = blockIdx.x * blockDim.x + threadIdx.x;
    if (v >= n) return;
    int beg = row[v], end = row[v + 1];
    for (int i = beg + 1; i < end; i++) {
        int key = csr[i];
        int j = i - 1;
        while (j >= beg && csr[j] > key) { csr[j + 1] = csr[j]; j--; }
        csr[j + 1] = key;
    }
    for (int i = beg; i < end; i++) csr[i] = src[csr[i]];
}

__global__ void count2_kernel(const int* __restrict__ src, const int* __restrict__ dst) {
    int e = blockIdx.x * blockDim.x + threadIdx.x;
    if (e >= EE) return;
    int ns = g_pos1[src[e]];
    int nd = g_pos1[dst[e]];
    if (ns >= 0 && nd >= 0) atomicAdd(&g_cnt2[nd], 1);
}

__global__ void degprep2_kernel() {
    int u = blockIdx.x * blockDim.x + threadIdx.x;
    if (u >= BK1) return;
    float d = __fadd_rn(1.0f, (float)g_cnt2[u]);
    g_dinv2[u] = __fdiv_rn(1.0f, __fsqrt_rn(d));
    g_invd2[u] = __fdiv_rn(1.0f, d);
}

__global__ void fill2_kernel(const int* __restrict__ src, const int* __restrict__ dst) {
    int e = blockIdx.x * blockDim.x + threadIdx.x;
    if (e >= EE) return;
    int ns = g_pos1[src[e]];
    int nd = g_pos1[dst[e]];
    if (ns >= 0 && nd >= 0) {
        int slot = g_row2[nd] + atomicAdd(&g_cur2[nd], 1);
        g_csr2[slot] = e;
    }
}

// fused: sort edge ids, then map edge id -> pos1[src[e]]
__global__ void sortmap2_kernel(const int* __restrict__ row, int* __restrict__ csr,
                                const int* __restrict__ src, int n) {
    int v = blockIdx.x * blockDim.x + threadIdx.x;
    if (v >= n) return;
    int beg = row[v], end = row[v + 1];
    for (int i = beg + 1; i < end; i++) {
        int key = csr[i];
        int j = i - 1;
        while (j >= beg && csr[j] > key) { csr[j + 1] = csr[j]; j--; }
        csr[j + 1] = key;
    }
    for (int i = beg; i < end; i++) csr[i] = g_pos1[src[csr[i]]];
}

// ---------------- dense matmul ----------------
// C[M,FOUT] = A[M,128] @ W[128,FOUT] (+bias)(+act). Even/odd-k parity chains, ascending.
template<int FOUT>
__global__ void mm_kernel(const float* __restrict__ A, const float* __restrict__ W,
                          const float* __restrict__ bias, float* __restrict__ C, int act) {
    constexpr int CP = FOUT / 32;
    __shared__ float As[64][32];
    __shared__ float Ws[32][FOUT];
    const int tid = threadIdx.x;
    const int rg = tid >> 5;
    const int lane = tid & 31;
    const int m0 = blockIdx.x * 64;

    float accA[8][CP], accB[8][CP];
#pragma unroll
    for (int r = 0; r < 8; r++)
#pragma unroll
        for (int c = 0; c < CP; c++) { accA[r][c] = 0.0f; accB[r][c] = 0.0f; }

    for (int kc = 0; kc < 128; kc += 32) {
        for (int i = tid; i < 512; i += 256) {
            int r = i >> 3, q = i & 7;
            ((float4*)(&As[r][0]))[q] = ((const float4*)(A + (size_t)(m0 + r) * 128 + kc))[q];
        }
        for (int i = tid; i < 32 * FOUT / 4; i += 256) {
            int r = i / (FOUT / 4), q = i % (FOUT / 4);
            ((float4*)(&Ws[r][0]))[q] = ((const float4*)(W + (size_t)(kc + r) * FOUT))[q];
        }
        __syncthreads();
#pragma unroll
        for (int k = 0; k < 32; k += 4) {
            float4 a4[8];
#pragma unroll
            for (int r = 0; r < 8; r++) a4[r] = *(const float4*)&As[rg * 8 + r][k];
#pragma unroll
            for (int kk = 0; kk < 4; kk++) {
                float wv[CP];
                if constexpr (CP == 4) {
                    float4 w4 = *(const float4*)&Ws[k + kk][lane * 4];
                    wv[0] = w4.x; wv[1] = w4.y; wv[2] = w4.z; wv[3] = w4.w;
                } else {
                    float2 w2 = *(const float2*)&Ws[k + kk][lane * 2];
                    wv[0] = w2.x; wv[1] = w2.y;
                }
#pragma unroll
                for (int r = 0; r < 8; r++) {
                    float av = (&a4[r].x)[kk];
                    if ((kk & 1) == 0) {
#pragma unroll
                        for (int c = 0; c < CP; c++) accA[r][c] = fmaf(av, wv[c], accA[r][c]);
                    } else {
#pragma unroll
                        for (int c = 0; c < CP; c++) accB[r][c] = fmaf(av, wv[c], accB[r][c]);
                    }
                }
            }
        }
        __syncthreads();
    }

#pragma unroll
    for (int r = 0; r < 8; r++) {
        int row = m0 + rg * 8 + r;
#pragma unroll
        for (int c = 0; c < CP; c++) {
            float v = __fadd_rn(accA[r][c], accB[r][c]);
            if (bias != nullptr) v = __fadd_rn(v, bias[lane * CP + c]);
            if (act == 1) v = fmaxf(v, 0.0f);
            else if (act == 2) v = xla_tanhf(v);
            C[(size_t)row * FOUT + lane * CP + c] = v;
        }
    }
}

// ---------------- GCN aggregation (sequential edge order, broadcast loads,
// identical __fmul_rn/__fadd_rn chain as before — bitwise-preserving) ----------------
__global__ void agg_kernel(const float* __restrict__ t, const int* __restrict__ row,
                           const int* __restrict__ csr, const float* __restrict__ dinv,
                           const float* __restrict__ invd, const float* __restrict__ bias,
                           float* __restrict__ out, int n, int act) {
    int v = (blockIdx.x * blockDim.x + threadIdx.x) >> 5;
    int lane = threadIdx.x & 31;
    if (v >= n) return;
    int beg = row[v], end = row[v + 1];
    float dv = dinv[v], iv = invd[v];
    float ax = 0.f, ay = 0.f, az = 0.f, aw = 0.f;
#pragma unroll 4
    for (int j = beg; j < end; j++) {
        int s = __ldg(&csr[j]);
        float w = __fmul_rn(__ldg(&dinv[s]), dv);        // norm = dinv[src]*dinv[dst]
        float4 h = *(const float4*)&t[(size_t)s * 128 + lane * 4];
        ax = __fadd_rn(ax, __fmul_rn(h.x, w));
        ay = __fadd_rn(ay, __fmul_rn(h.y, w));
        az = __fadd_rn(az, __fmul_rn(h.z, w));
        aw = __fadd_rn(aw, __fmul_rn(h.w, w));
    }
    float4 tv = *(const float4*)&t[(size_t)v * 128 + lane * 4];
    float4 b4 = *(const float4*)&bias[lane * 4];
    float o0 = __fadd_rn(__fadd_rn(ax, __fmul_rn(tv.x, iv)), b4.x);
    float o1 = __fadd_rn(__fadd_rn(ay, __fmul_rn(tv.y, iv)), b4.y);
    float o2 = __fadd_rn(__fadd_rn(az, __fmul_rn(tv.z, iv)), b4.z);
    float o3 = __fadd_rn(__fadd_rn(aw, __fmul_rn(tv.w, iv)), b4.w);
    if (act == 1) { o0 = fmaxf(o0, 0.f); o1 = fmaxf(o1, 0.f); o2 = fmaxf(o2, 0.f); o3 = fmaxf(o3, 0.f); }
    else if (act == 2) { o0 = xla_tanhf(o0); o1 = xla_tanhf(o1); o2 = xla_tanhf(o2); o3 = xla_tanhf(o3); }
    *(float4*)&out[(size_t)v * 128 + lane * 4] = make_float4(o0, o1, o2, o3);
}

// lin[v] = A[v,:128]·w — 4 strided lanes + reduce (l0+l2)+(l1+l3)
__global__ void dot128_kernel(const float* __restrict__ A, const float* __restrict__ w,
                              float* __restrict__ out, int M) {
    int v = blockIdx.x * blockDim.x + threadIdx.x;
    if (v >= M) return;
    const float* a = A + (size_t)v * 128;
    float l0 = 0.f, l1 = 0.f, l2 = 0.f, l3 = 0.f;
#pragma unroll 8
    for (int k = 0; k < 128; k += 4) {
        l0 = fmaf(a[k],     __ldg(&w[k]),     l0);
        l1 = fmaf(a[k + 1], __ldg(&w[k + 1]), l1);
        l2 = fmaf(a[k + 2], __ldg(&w[k + 2]), l2);
        l3 = fmaf(a[k + 3], __ldg(&w[k + 3]), l3);
    }
    out[v] = __fadd_rn(__fadd_rn(l0, l2), __fadd_rn(l1, l3));
}

// score[v], fp32, sequential edge order, mul/add separate
__global__ void scoreagg_kernel(const float* __restrict__ lin, const int* __restrict__ row,
                                const int* __restrict__ csr, const float* __restrict__ dinv,
                                const float* __restrict__ invd, const float* __restrict__ bias,
                                float* __restrict__ score, int n) {
    int v = blockIdx.x * blockDim.x + threadIdx.x;
    if (v >= n) return;
    int beg = row[v], end = row[v + 1];
    float dv = dinv[v];
    float acc = 0.0f;
    for (int j = beg; j < end; j++) {
        int s = csr[j];
        float w = __fmul_rn(dinv[s], dv);
        acc = __fadd_rn(acc, __fmul_rn(lin[s], w));
    }
    score[v] = __fadd_rn(__fadd_rn(acc, __fmul_rn(lin[v], invd[v])), bias[0]);
}

// per-graph bitonic sort: fp32 score desc; exact ties -> lower index first.
// Optional near-tie canonicalization with relative threshold thr_rel (0 disables).
template<int NP>
__global__ void topk_kernel(const float* __restrict__ score, int* __restrict__ perm,
                            int* __restrict__ pos, int kkeep, float thr_rel) {
    __shared__ float ss[NP];
    __shared__ int   si[NP];
    int b = blockIdx.x, tid = threadIdx.x;
    for (int i = tid; i < NP; i += blockDim.x) {
        ss[i] = score[b * NP + i];
        si[i] = i;
        pos[b * NP + i] = -1;
    }
    __syncthreads();
    for (int k = 2; k <= NP; k <<= 1) {
        for (int j = k >> 1; j > 0; j >>= 1) {
            for (int i = tid; i < NP; i += blockDim.x) {
                int ixj = i ^ j;
                if (ixj > i) {
                    float sa = ss[i], sb = ss[ixj];
                    int ia = si[i], ib = si[ixj];
                    bool b_first = (sb > sa) || (sb == sa && ib < ia);
                    bool a_first = (sa > sb) || (sa == sb && ia < ib);
                    bool sw = ((i & k) == 0) ? b_first : a_first;
                    if (sw) { ss[i] = sb; ss[ixj] = sa; si[i] = ib; si[ixj] = ia; }
                }
            }
            __syncthreads();
        }
    }
    if (tid == 0 && thr_rel > 0.0f) {
        for (int pass = 0; pass < 6; pass++) {
            bool any = false;
            for (int p = 0; p < NP - 1; p++) {
                float a = ss[p], c = ss[p + 1];
                if (a > c) {
                    float gap = __fadd_rn(a, -c);
                    float thr = thr_rel * fmaxf(fabsf(a), fabsf(c));
                    if (gap <= thr && si[p] > si[p + 1]) {
                        ss[p] = c; ss[p + 1] = a;
                        int t2 = si[p]; si[p] = si[p + 1]; si[p + 1] = t2;
                        any = true;
                    }
                }
            }
            if (!any) break;
        }
    }
    __syncthreads();
    for (int i = tid; i < kkeep; i += blockDim.x) {
        int g = b * NP + si[i];
        perm[b * kkeep + i] = g;
        pos[g] = b * kkeep + i;
    }
}

__global__ void gate_kernel(const float* __restrict__ h, const float* __restrict__ score,
                            const int* __restrict__ perm, float* __restrict__ xp, int rows) {
    int gid = blockIdx.x * blockDim.x + threadIdx.x;
    if (gid >= rows * 128) return;
    int j = gid >> 7, c = gid & 127;
    int v = perm[j];
    float tg = xla_tanhf(score[v]);
    xp[gid] = __fmul_rn(h[(size_t)v * 128 + c], tg);
}

// fused unpool-from-gate: out[v,c] = pos[v]>=0 ? h[v,c]*tanh(score[v]) : 0
// (bitwise equal to unpool(gate(...)) since same __fmul_rn(h, tanh))
__global__ void unpoolg_kernel(const float* __restrict__ h, const float* __restrict__ score,
                               const int* __restrict__ pos, float* __restrict__ out, int rows) {
    int gid = blockIdx.x * blockDim.x + threadIdx.x;
    if (gid >= rows * 128) return;
    int v = gid >> 7;
    int p = pos[v];
    float val = 0.0f;
    if (p >= 0) val = __fmul_rn(h[gid], xla_tanhf(score[v]));
    out[gid] = val;
}

// composed double unpool: xoutF[v,c] = pos1[v]>=0 && pos2[pos1[v]]>=0 ? xp2[pos2[pos1[v]],c] : 0
__global__ void unpool2_kernel(const float* __restrict__ xp2, float* __restrict__ out) {
    int gid = blockIdx.x * blockDim.x + threadIdx.x;
    if (gid >= NN * 128) return;
    int v = gid >> 7, c = gid & 127;
    int p1 = g_pos1[v];
    float val = 0.0f;
    if (p1 >= 0) {
        int p2 = g_pos2[p1];
        if (p2 >= 0) val = xp2[(size_t)p2 * 128 + c];
    }
    out[gid] = val;
}

__global__ void pool_stats_kernel(const float* __restrict__ xp, float* __restrict__ g, int kk) {
    int b = blockIdx.x, c = threadIdx.x;
    float mx = -3.402823466e38f, sm = 0.f;
    const float* base = xp + (size_t)b * kk * 128;
    for (int r = 0; r < kk; r++) {
        float v = base[(size_t)r * 128 + c];
        mx = fmaxf(mx, v);
        sm = __fadd_rn(sm, v);
    }
    g[b * 256 + c] = mx;
    g[b * 256 + 128 + c] = __fdiv_rn(sm, (float)kk);
}

__global__ void gather_kernel(const int* __restrict__ perm, float* __restrict__ og,
                              float* __restrict__ op, int cnt) {
    int j = blockIdx.x * blockDim.x + threadIdx.x;
    if (j >= cnt) return;
    int v = perm[j];
    og[j] = g_deggt[v];
    op[j] = g_xdeg[v];
}

__global__ void mlp641_kernel(const float* __restrict__ in, const float* __restrict__ w,
                              const float* __restrict__ bptr, float* __restrict__ out, int M) {
    int v = blockIdx.x * blockDim.x + threadIdx.x;
    if (v >= M) return;
    const float* a = in + (size_t)v * 64;
    float l0 = 0.f, l1 = 0.f, l2 = 0.f, l3 = 0.f;
#pragma unroll
    for (int k = 0; k < 64; k += 4) {
        l0 = fmaf(a[k],     __ldg(&w[k]),     l0);
        l1 = fmaf(a[k + 1], __ldg(&w[k + 1]), l1);
        l2 = fmaf(a[k + 2], __ldg(&w[k + 2]), l2);
        l3 = fmaf(a[k + 3], __ldg(&w[k + 3]), l3);
    }
    float acc = __fadd_rn(__fadd_rn(l0, l2), __fadd_rn(l1, l3));
    acc = __fadd_rn(acc, bptr[0]);
    out[v] = fmaxf(acc, 0.f);
}

__global__ void head_kernel(const float* __restrict__ wl1, const float* __restrict__ bl1,
                            const float* __restrict__ wl2, const float* __restrict__ bl2,
                            const float* __restrict__ wl3, const float* __restrict__ bl3,
                            float* __restrict__ ocls) {
    __shared__ float gg[256];
    __shared__ float ga[128];
    __shared__ float gb[64];
    int b = blockIdx.x, t = threadIdx.x;
    gg[t]       = g_g1[b * 256 + t]       + g_g2[b * 256 + t];
    gg[t + 128] = g_g1[b * 256 + 128 + t] + g_g2[b * 256 + 128 + t];
    __syncthreads();
    float acc = 0.0f;
    for (int k = 0; k < 256; k++) acc = fmaf(gg[k], wl1[k * 128 + t], acc);
    ga[t] = fmaxf(acc + bl1[t], 0.f);
    __syncthreads();
    if (t < 64) {
        float a2 = 0.0f;
        for (int k = 0; k < 128; k++) a2 = fmaf(ga[k], wl2[k * 64 + t], a2);
        gb[t] = fmaxf(a2 + bl2[t], 0.f);
    }
    __syncthreads();
    if (t < 10) {
        float a3 = 0.0f;
        for (int k = 0; k < 64; k++) a3 = fmaf(gb[k], wl3[k * 10 + t], a3);
        ocls[b * 10 + t] = a3 + bl3[t];
    }
}

// ---------------- host ----------------
static void* devp(const void* sym) {
    void* p = nullptr;
    cudaGetSymbolAddress(&p, sym);
    return p;
}

extern "C" void kernel_launch(void* const* d_in, const int* in_sizes, int n_in,
                              void* d_out, int out_size) {
    const float* x     = (const float*)d_in[0];
    const int*   esrc  = (const int*)d_in[1];
    const int*   edst  = (const int*)d_in[2];
    const float* w_c1 = (const float*)d_in[3];  const float* b_c1 = (const float*)d_in[4];
    const float* w_c2 = (const float*)d_in[5];  const float* b_c2 = (const float*)d_in[6];
    const float* w_c3 = (const float*)d_in[7];  const float* b_c3 = (const float*)d_in[8];
    const float* w_c4 = (const float*)d_in[9];  const float* b_c4 = (const float*)d_in[10];
    const float* w_c5 = (const float*)d_in[11]; const float* b_c5 = (const float*)d_in[12];
    const float* w_p1 = (const float*)d_in[13]; const float* b_p1 = (const float*)d_in[14];
    const float* w_p2 = (const float*)d_in[15]; const float* b_p2 = (const float*)d_in[16];
    const float* w_l1 = (const float*)d_in[17]; const float* b_l1 = (const float*)d_in[18];
    const float* w_l2 = (const float*)d_in[19]; const float* b_l2 = (const float*)d_in[20];
    const float* w_l3 = (const float*)d_in[21]; const float* b_l3 = (const float*)d_in[22];
    const float* w_l4 = (const float*)d_in[23]; const float* b_l4 = (const float*)d_in[24];
    const float* w_l5 = (const float*)d_in[25]; const float* b_l5 = (const float*)d_in[26];
    const float* w_l6 = (const float*)d_in[27]; const float* b_l6 = (const float*)d_in[28];

    float* out = (float*)d_out;
    float* o_cls  = out;
    float* o_dec1 = out + 320;
    float* o_dec2 = o_dec1 + (size_t)NN * FH;
    float* o_dgt1 = o_dec2 + (size_t)NN * FH;
    float* o_dpr1 = o_dgt1 + BK1;
    float* o_dgt2 = o_dpr1 + BK1;
    float* o_dpr2 = o_dgt2 + BK2;

    float* p_t     = (float*)devp(g_t);
    float* p_h1    = (float*)devp(g_h1);
    float* p_a     = (float*)devp(g_a);
    float* p_bf    = (float*)devp(g_bf);
    float* p_xout  = (float*)devp(g_xout);
    float* p_xoutF = (float*)devp(g_xoutF);
    float* p_mA    = (float*)devp(g_mA);
    float* p_mB    = (float*)devp(g_mB);
    float* p_xp1   = (float*)devp(g_xp1);
    float* p_t2    = (float*)devp(g_t2);
    float* p_h2    = (float*)devp(g_h2);
    float* p_xp2   = (float*)devp(g_xp2);
    float* p_lin   = (float*)devp(g_lin);
    float* p_sc1   = (float*)devp(g_sc1);
    float* p_sc2   = (float*)devp(g_sc2);
    float* p_xdeg  = (float*)devp(g_xdeg);
    float* p_dinv1 = (float*)devp(g_dinv1);
    float* p_invd1 = (float*)devp(g_invd1);
    float* p_dinv2 = (float*)devp(g_dinv2);
    float* p_invd2 = (float*)devp(g_invd2);
    int*   p_cntD  = (int*)devp(g_cntD);
    int*   p_row1  = (int*)devp(g_row1);
    int*   p_csr1  = (int*)devp(g_csr1);
    int*   p_cnt2  = (int*)devp(g_cnt2);
    int*   p_row2  = (int*)devp(g_row2);
    int*   p_csr2  = (int*)devp(g_csr2);
    int*   p_perm1 = (int*)devp(g_perm1);
    int*   p_pos1  = (int*)devp(g_pos1);
    int*   p_perm2 = (int*)devp(g_perm2);
    int*   p_pos2  = (int*)devp(g_pos2);
    float* p_g1    = (float*)devp(g_g1);
    float* p_g2    = (float*)devp(g_g2);

    // ---- level 1 prep (mm placed at launch index 5 for ncu visibility) ----
    zero_counts_kernel<<<NN / 256, 256>>>();                          // 0
    count_kernel<<<EE / 256, 256>>>(esrc, edst);                      // 1
    degprep1_kernel<<<NN / 256, 256>>>();                             // 2
    scan_kernel<NN><<<1, 1024>>>(p_cntD, p_row1);                     // 3
    fill1_kernel<<<EE / 256, 256>>>(esrc, edst);                      // 4
    mm_kernel<128><<<NN / 64, 256>>>(x, w_c1, nullptr, p_t, 0);       // 5 <- profiled
    sortmap1_kernel<<<NN / 256, 256>>>(p_row1, p_csr1, esrc, NN);     // 6
    agg_kernel<<<NN / 8, 256>>>(p_t, p_row1, p_csr1, p_dinv1, p_invd1, b_c1, p_h1, NN, 1);

    // ---- SAGPool level 1 ----
    dot128_kernel<<<NN / 256, 256>>>(p_h1, w_p1, p_lin, NN);
    scoreagg_kernel<<<NN / 256, 256>>>(p_lin, p_row1, p_csr1, p_dinv1, p_invd1, b_p1, p_sc1, NN);
    topk_kernel<1024><<<BB, 512>>>(p_sc1, p_perm1, p_pos1, K1c, 6e-7f);
    gate_kernel<<<(BK1 * 128) / 256, 256>>>(p_h1, p_sc1, p_perm1, p_xp1, BK1);
    unpoolg_kernel<<<(NN * 128) / 256, 256>>>(p_h1, p_sc1, p_pos1, p_xout, NN);

    // ---- decoder 1 -> o_dec1 ----
    mm_kernel<128><<<NN / 64, 256>>>(p_xout, w_c3, nullptr, p_t, 0);
    agg_kernel<<<NN / 8, 256>>>(p_t, p_row1, p_csr1, p_dinv1, p_invd1, b_c3, p_a, NN, 2);
    mm_kernel<128><<<NN / 64, 256>>>(p_a, w_c4, nullptr, p_t, 0);
    agg_kernel<<<NN / 8, 256>>>(p_t, p_row1, p_csr1, p_dinv1, p_invd1, b_c4, p_bf, NN, 2);
    mm_kernel<128><<<NN / 64, 256>>>(p_bf, w_c5, nullptr, p_t, 0);
    agg_kernel<<<NN / 8, 256>>>(p_t, p_row1, p_csr1, p_dinv1, p_invd1, b_c5, o_dec1, NN, 0);

    // ---- degree mlp ----
    mm_kernel<128><<<NN / 64, 256>>>(p_xout, w_l4, b_l4, p_mA, 1);
    mm_kernel<64><<<NN / 64, 256>>>(p_mA, w_l5, b_l5, p_mB, 1);
    mlp641_kernel<<<NN / 256, 256>>>(p_mB, w_l6, b_l6, p_xdeg, NN);
    gather_kernel<<<BK1 / 256, 256>>>(p_perm1, o_dgt1, o_dpr1, BK1);
    pool_stats_kernel<<<BB, 128>>>(p_xp1, p_g1, K1c);

    // ---- level 2 graph ----
    count2_kernel<<<EE / 256, 256>>>(esrc, edst);
    degprep2_kernel<<<BK1 / 256, 256>>>();
    scan_kernel<BK1><<<1, 1024>>>(p_cnt2, p_row2);
    fill2_kernel<<<EE / 256, 256>>>(esrc, edst);
    sortmap2_kernel<<<BK1 / 256, 256>>>(p_row2, p_csr2, esrc, BK1);

    // h2 = relu(gcn(xp1, w_c2))
    mm_kernel<128><<<BK1 / 64, 256>>>(p_xp1, w_c2, nullptr, p_t2, 0);
    agg_kernel<<<BK1 / 8, 256>>>(p_t2, p_row2, p_csr2, p_dinv2, p_invd2, b_c2, p_h2, BK1, 1);

    // SAGPool level 2 (pure fp32 order + exact-tie lower-index)
    dot128_kernel<<<BK1 / 256, 256>>>(p_h2, w_p2, p_lin, BK1);
    scoreagg_kernel<<<BK1 / 256, 256>>>(p_lin, p_row2, p_csr2, p_dinv2, p_invd2, b_p2, p_sc2, BK1);
    topk_kernel<512><<<BB, 512>>>(p_sc2, p_perm2, p_pos2, K2c, 0.0f);
    gate_kernel<<<(BK2 * 128) / 256, 256>>>(p_h2, p_sc2, p_perm2, p_xp2, BK2);
    unpool2_kernel<<<(NN * 128) / 256, 256>>>(p_xp2, p_xoutF);
    gather_kernel<<<BK2 / 256, 256>>>(p_perm2, o_dgt2, o_dpr2, BK2);
    pool_stats_kernel<<<BB, 128>>>(p_xp2, p_g2, K2c);

    // ---- decoder 2 -> o_dec2 ----
    mm_kernel<128><<<NN / 64, 256>>>(p_xoutF, w_c3, nullptr, p_t, 0);
    agg_kernel<<<NN / 8, 256>>>(p_t, p_row1, p_csr1, p_dinv1, p_invd1, b_c3, p_a, NN, 2);
    mm_kernel<128><<<NN / 64, 256>>>(p_a, w_c4, nullptr, p_t, 0);
    agg_kernel<<<NN / 8, 256>>>(p_t, p_row1, p_csr1, p_dinv1, p_invd1, b_c4, p_bf, NN, 2);
    mm_kernel<128><<<NN / 64, 256>>>(p_bf, w_c5, nullptr, p_t, 0);
    agg_kernel<<<NN / 8, 256>>>(p_t, p_row1, p_csr1, p_dinv1, p_invd1, b_c5, o_dec2, NN, 0);

    // ---- classification head ----
    head_kernel<<<BB, 128>>>(w_l1, b_l1, w_l2, b_l2, w_l3, b_l3, o_cls);
}